// round 15
// baseline (speedup 1.0000x reference)
#include <cuda_runtime.h>
#include <cuda_fp16.h>

#define NB 256
#define NT 1024
#define NV 5000
#define ND 100
#define NH 64
#define NC 2

// Scratch: EW = E @ W + b, [V, H], stored as FP16 (cvt done here, off the
// RNN critical path). 640 KB -> fully L2-resident.
__device__ __half g_EWh[NV * NH];

// ---------------------------------------------------------------------------
// Kernel A: EWh[v][j] = (half) (sum_d E[v][d] * W[d][j] + b[j])
// ---------------------------------------------------------------------------
__global__ void ew_kernel(const float* __restrict__ E,
                          const float* __restrict__ W,
                          const float* __restrict__ bias) {
    int v = blockIdx.x * 4 + (threadIdx.x >> 6);
    int j = threadIdx.x & 63;
    if (v >= NV) return;
    float acc = bias[j];
    const float* e = E + v * ND;
    #pragma unroll 4
    for (int d = 0; d < ND; d++)
        acc = fmaf(e[d], W[d * NH + j], acc);
    g_EWh[v * NH + j] = __float2half(acc);
}

// HW tanh on fp16 (MUFU.TANH, sm_75+): lat 16, single instruction.
__device__ __forceinline__ __half tanh_fast_h(__half x) {
    __half y;
    asm("tanh.approx.f16 %0, %1;"
        : "=h"(*reinterpret_cast<unsigned short*>(&y))
        : "h"(*reinterpret_cast<const unsigned short*>(&x)));
    return y;
}

// 16-byte chunk of 4 half2 (8 h-values) -> one LDS.128.
struct __align__(16) H2x4 { __half2 a, b, c, d; };

// ---------------------------------------------------------------------------
// Kernel B: masked tanh RNN, T=1024 steps + mean-pool + dense + sigmoid.
// STRUCTURE = R4/R13 winner (156us): 256 blocks x 128 thr, K-split by 2
// in-warp, lanes (l, l+16) of warp w own output j = 16w + (l&15), packed
// fp16 dot (16 HFMA2 + hadd2 tree, 4x LDS.128), one __syncthreads/step.
// R15 delta: the ENTIRE tail runs in fp16 — merge the K-halves by
// shuffling the packed half2 partial (32-bit shfl) + hadd2, fold halves
// and ew with HADDs, tanh.approx.f16, select and STS.16 in half. This
// removes both ~20-cyc F2F cvts (h2->f32 before merge, f32->f16 before
// store) and two f32 adds from the per-step critical path. ew comes from
// the fp16 EW table so its cvt lives in kernel A. s accumulates in f32
// via one off-path cvt (s is only read at the end).
// ---------------------------------------------------------------------------
__global__ void __launch_bounds__(128) rnn_kernel(
    const int* __restrict__ tokens,
    const float* __restrict__ U,
    const float* __restrict__ Wd,
    const float* __restrict__ bd,
    float* __restrict__ out)
{
    __shared__ __align__(16) __half hbuf[2][NH];
    __shared__ float red[4][2];
    const int w     = threadIdx.x >> 5;
    const int l     = threadIdx.x & 31;
    const int j     = w * 16 + (l & 15);
    const int kbase = (l >> 4) * 32;       // this lane's K-half
    const bool low  = (l < 16);
    const int b     = blockIdx.x;

    // U K-pairs for this lane's half, packed half2 in natural memory order.
    __half2 Upk[16];
    #pragma unroll
    for (int m = 0; m < 16; m++) {
        float ua = U[(kbase + 2 * m)     * NH + j];
        float ub = U[(kbase + 2 * m + 1) * NH + j];
        Upk[m] = __floats2half2_rn(ua, ub);
    }

    if (threadIdx.x < NH) hbuf[0][threadIdx.x] = __float2half(0.f);
    __syncthreads();

    const int* trow = tokens + b * NT;
    __half h = __float2half(0.f);
    float s = 0.f;

    // Pipeline: tokens 3 ahead, EW rows 2 ahead (2 steps >= L2 ~234cyc).
    int tok0 = trow[0];
    int tok1 = trow[1];
    int tok2 = trow[2];
    __half ew0 = g_EWh[tok0 * NH + j];
    __half ew1 = g_EWh[tok1 * NH + j];

    #pragma unroll 2
    for (int t = 0; t < NT; t++) {
        int t3 = (t + 3 < NT) ? (t + 3) : (NT - 1);
        int tok3 = trow[t3];
        __half ew2 = g_EWh[tok2 * NH + j];

        // Partial dot over this lane's K-half, packed fp16. 4x LDS.128.
        const H2x4* hp = reinterpret_cast<const H2x4*>(hbuf[t & 1] + kbase);
        H2x4 v0 = hp[0], v1 = hp[1], v2 = hp[2], v3 = hp[3];
        __half2 z  = __float2half2_rn(0.f);
        __half2 A0 = z, A1 = z, A2 = z, A3 = z;
        __half2 A4 = z, A5 = z, A6 = z, A7 = z;
        A0 = __hfma2(v0.a, Upk[0],  A0);  A1 = __hfma2(v0.b, Upk[1],  A1);
        A2 = __hfma2(v0.c, Upk[2],  A2);  A3 = __hfma2(v0.d, Upk[3],  A3);
        A4 = __hfma2(v1.a, Upk[4],  A4);  A5 = __hfma2(v1.b, Upk[5],  A5);
        A6 = __hfma2(v1.c, Upk[6],  A6);  A7 = __hfma2(v1.d, Upk[7],  A7);
        A0 = __hfma2(v2.a, Upk[8],  A0);  A1 = __hfma2(v2.b, Upk[9],  A1);
        A2 = __hfma2(v2.c, Upk[10], A2);  A3 = __hfma2(v2.d, Upk[11], A3);
        A4 = __hfma2(v3.a, Upk[12], A4);  A5 = __hfma2(v3.b, Upk[13], A5);
        A6 = __hfma2(v3.c, Upk[14], A6);  A7 = __hfma2(v3.d, Upk[15], A7);
        __half2 B0 = __hadd2(A0, A1), B1 = __hadd2(A2, A3);
        __half2 B2 = __hadd2(A4, A5), B3 = __hadd2(A6, A7);
        __half2 C0 = __hadd2(B0, B1), C1 = __hadd2(B2, B3);
        __half2 D  = __hadd2(C0, C1);          // (even-k sum, odd-k sum)

        // Merge K-halves IN FP16: shfl the packed half2 partial (32-bit).
        unsigned int du = *reinterpret_cast<unsigned int*>(&D);
        unsigned int qu = __shfl_xor_sync(0xffffffffu, du, 16);
        __half2 D2 = __hadd2(D, *reinterpret_cast<__half2*>(&qu));
        // Fold halves + ew, all HADD (half-lane selectors, 4cyc each).
        __half a_h = __hadd(__hadd(__low2half(D2), __high2half(D2)), ew0);
        __half hn  = tanh_fast_h(a_h);

        // Masked recurrence: token 0 carries previous state (block-uniform).
        if (tok0 != 0) h = hn;
        s += __half2float(h);                  // off the recurrence path

        // Publish into the other buffer (one writer per output).
        if (low) hbuf[(t & 1) ^ 1][j] = h;
        __syncthreads();

        tok0 = tok1; tok1 = tok2; tok2 = tok3;
        ew0 = ew1;  ew1 = ew2;
    }

    // Epilogue: mean pool -> dense (64 -> 2) -> sigmoid. Output j is held by
    // 2 lanes; count only l<16.
    float p  = s * (1.0f / NT);
    float c0 = low ? p * Wd[j * NC + 0] : 0.f;
    float c1 = low ? p * Wd[j * NC + 1] : 0.f;
    #pragma unroll
    for (int off = 16; off; off >>= 1) {
        c0 += __shfl_xor_sync(0xffffffffu, c0, off);
        c1 += __shfl_xor_sync(0xffffffffu, c1, off);
    }
    if (l == 0) { red[w][0] = c0; red[w][1] = c1; }
    __syncthreads();
    if (threadIdx.x == 0) {
        float C0 = red[0][0] + red[1][0] + red[2][0] + red[3][0] + bd[0];
        float C1 = red[0][1] + red[1][1] + red[2][1] + red[3][1] + bd[1];
        out[b * NC + 0] = 1.0f / (1.0f + expf(-C0));
        out[b * NC + 1] = 1.0f / (1.0f + expf(-C1));
    }
}

// ---------------------------------------------------------------------------
extern "C" void kernel_launch(void* const* d_in, const int* in_sizes, int n_in,
                              void* d_out, int out_size) {
    const int*   tokens = (const int*)  d_in[0];
    const float* E      = (const float*)d_in[1];
    const float* W      = (const float*)d_in[2];
    const float* U      = (const float*)d_in[3];
    const float* bias   = (const float*)d_in[4];
    const float* Wd     = (const float*)d_in[5];
    const float* bd     = (const float*)d_in[6];
    float* out = (float*)d_out;

    ew_kernel<<<(NV + 3) / 4, 256>>>(E, W, bias);
    rnn_kernel<<<NB, 128>>>(tokens, U, Wd, bd, out);
}